// round 6
// baseline (speedup 1.0000x reference)
#include <cuda_runtime.h>

#define ND 128
#define ED 64
#define TE 128
#define MAXN 50000

typedef unsigned long long ull;
typedef const ulonglong2* u2p;

// scratch (static device arrays: allocation-free).
// __align__(256): accessed as float4 / red.global.add.v4.f32 (need >=16B).
__device__ __align__(256) float g_P[MAXN * ND];    // node_feats @ msg_w1[:128]
__device__ __align__(256) float g_agg[MAXN * ND];  // scatter-add accumulator
__device__ __align__(256) float g_H2[MAXN * ND];   // update hidden

__device__ __forceinline__ ull pack2(float x, float y) {
    ull r; asm("mov.b64 %0, {%1, %2};" : "=l"(r) : "f"(x), "f"(y)); return r;
}
__device__ __forceinline__ void unpack2(ull v, float& x, float& y) {
    asm("mov.b64 {%0, %1}, %2;" : "=f"(x), "=f"(y) : "l"(v));
}
__device__ __forceinline__ void fma2(ull& acc, ull a, ull b) {
    asm("fma.rn.f32x2 %0, %1, %2, %0;" : "+l"(acc) : "l"(a), "l"(b));
}
__device__ __forceinline__ float lrelu(float x) { return x >= 0.f ? x : 0.2f * x; }

// ---------------------------------------------------------------------------
__global__ void zero_kernel(int n4) {
    int i = blockIdx.x * blockDim.x + threadIdx.x;
    if (i < n4) ((float4*)g_agg)[i] = make_float4(0.f, 0.f, 0.f, 0.f);
}

// ---------------------------------------------------------------------------
// P = node_feats @ msg_w1[0:128, :]   (no bias)
__global__ __launch_bounds__(256, 1) void p_kernel(
    const float* __restrict__ nf, const float* __restrict__ w1, int N)
{
    extern __shared__ char smraw[];
    float* sw   = (float*)smraw;      // 128*128
    float* sin_ = sw + 16384;         // 64*129
    int tid = threadIdx.x;
    int n0 = blockIdx.x * 64;

    for (int i = tid; i < 4096; i += 256)
        ((float4*)sw)[i] = ((const float4*)w1)[i];
    for (int i = tid; i < 64 * 32; i += 256) {
        int r = i >> 5, q = i & 31, gn = n0 + r;
        float4 v = (gn < N) ? ((const float4*)nf)[(size_t)gn * 32 + q]
                            : make_float4(0.f, 0.f, 0.f, 0.f);
        float* p = sin_ + r * 129 + q * 4;
        p[0] = v.x; p[1] = v.y; p[2] = v.z; p[3] = v.w;
    }
    __syncthreads();

    int n = tid & 63, c0 = (tid >> 6) * 32;
    ull acc[16];
#pragma unroll
    for (int i = 0; i < 16; i++) acc[i] = pack2(0.f, 0.f);
#pragma unroll 4
    for (int k = 0; k < 128; k++) {
        float a = sin_[n * 129 + k];
        ull a2 = pack2(a, a);
        u2p wr = (u2p)(sw + k * ND + c0);
#pragma unroll
        for (int i = 0; i < 8; i++) {
            ulonglong2 w = wr[i];
            fma2(acc[2 * i], a2, w.x);
            fma2(acc[2 * i + 1], a2, w.y);
        }
    }
    int gn = n0 + n;
    if (gn < N) {
        float4* pr = (float4*)(g_P + (size_t)gn * ND + c0);
#pragma unroll
        for (int i = 0; i < 8; i++) {
            float x, y, z, w_;
            unpack2(acc[2 * i], x, y); unpack2(acc[2 * i + 1], z, w_);
            pr[i] = make_float4(x, y, z, w_);
        }
    }
}

// ---------------------------------------------------------------------------
// Fused edge kernel:
//   h = lrelu(P[dst] + edge_feats @ w1[128:192] + b1)
//   messages = h @ w2 + b2
//   atomic scatter-add into g_agg[src]
__global__ __launch_bounds__(512, 1) void edge_kernel(
    const float* __restrict__ ef,
    const float* __restrict__ w1, const float* __restrict__ b1,
    const float* __restrict__ w2, const float* __restrict__ b2,
    const int* __restrict__ eidx,   // int32! (JAX x64-disabled downgrades int64)
    int N, int E)
{
    extern __shared__ char smraw[];
    float* sw1e = (float*)smraw;       // 64*128   = 8192 floats
    float* sw2  = sw1e + 8192;         // 128*128  = 16384
    float* sb1  = sw2 + 16384;         // 128
    float* sb2  = sb1 + 128;           // 128
    float* sef  = sb2 + 128;           // 128*65   = 8320
    float* sh   = sef + 8320;          // 128*129  = 16512
    int*   ssrc = (int*)(sh + 16512);  // 128
    int*   sdst = ssrc + 128;          // 128

    int tid = threadIdx.x;
    int e0 = blockIdx.x * TE;

    for (int i = tid; i < 2048; i += 512)
        ((float4*)sw1e)[i] = ((const float4*)(w1 + 128 * ND))[i];
    for (int i = tid; i < 4096; i += 512)
        ((float4*)sw2)[i] = ((const float4*)w2)[i];
    if (tid < 32)       ((float4*)sb1)[tid]      = ((const float4*)b1)[tid];
    else if (tid < 64)  ((float4*)sb2)[tid - 32] = ((const float4*)b2)[tid - 32];
    for (int i = tid; i < TE; i += 512) {
        int ge = e0 + i;
        if (ge < E) {
            int s = eidx[ge];
            int d = eidx[E + ge];
            ssrc[i] = ((unsigned)s < (unsigned)N) ? s : -1;
            sdst[i] = ((unsigned)d < (unsigned)N) ? d : 0;
        } else { ssrc[i] = -1; sdst[i] = 0; }
    }
    for (int i = tid; i < TE * 16; i += 512) {
        int r = i >> 4, q = i & 15, ge = e0 + r;
        float4 v = (ge < E) ? ((const float4*)ef)[(size_t)ge * 16 + q]
                            : make_float4(0.f, 0.f, 0.f, 0.f);
        float* p = sef + r * 65 + q * 4;
        p[0] = v.x; p[1] = v.y; p[2] = v.z; p[3] = v.w;
    }
    __syncthreads();

    int e = tid & (TE - 1), c0 = (tid >> 7) * 32;

    // phase A: edge-part GEMM (K=64) + P gather + bias + leaky -> sh
    ull acc[16];
#pragma unroll
    for (int i = 0; i < 16; i++) acc[i] = pack2(0.f, 0.f);
#pragma unroll 4
    for (int k = 0; k < ED; k++) {
        float a = sef[e * 65 + k];
        ull a2 = pack2(a, a);
        u2p wr = (u2p)(sw1e + k * ND + c0);
#pragma unroll
        for (int i = 0; i < 8; i++) {
            ulonglong2 w = wr[i];
            fma2(acc[2 * i], a2, w.x);
            fma2(acc[2 * i + 1], a2, w.y);
        }
    }
    {
        int d = sdst[e];
        const float4* pr = (const float4*)(g_P + (size_t)d * ND + c0);
        const float4* br = (const float4*)(sb1 + c0);
        float* hrow = sh + e * 129 + c0;
#pragma unroll
        for (int i = 0; i < 8; i++) {
            float4 p = pr[i];
            float4 bb = br[i];
            float x, y, z, w_;
            unpack2(acc[2 * i], x, y); unpack2(acc[2 * i + 1], z, w_);
            x = lrelu(x + p.x + bb.x);
            y = lrelu(y + p.y + bb.y);
            z = lrelu(z + p.z + bb.z);
            w_ = lrelu(w_ + p.w + bb.w);
            hrow[4 * i] = x; hrow[4 * i + 1] = y;
            hrow[4 * i + 2] = z; hrow[4 * i + 3] = w_;
        }
    }
    __syncthreads();

    // phase B: messages = h @ w2 + b2, scatter-add
#pragma unroll
    for (int i = 0; i < 16; i++) acc[i] = pack2(0.f, 0.f);
#pragma unroll 4
    for (int k = 0; k < ND; k++) {
        float a = sh[e * 129 + k];
        ull a2 = pack2(a, a);
        u2p wr = (u2p)(sw2 + k * ND + c0);
#pragma unroll
        for (int i = 0; i < 8; i++) {
            ulonglong2 w = wr[i];
            fma2(acc[2 * i], a2, w.x);
            fma2(acc[2 * i + 1], a2, w.y);
        }
    }
    {
        int s = ssrc[e];
        if (s >= 0) {
            const float4* br = (const float4*)(sb2 + c0);
            float* ar = g_agg + (size_t)s * ND + c0;
#pragma unroll
            for (int i = 0; i < 8; i++) {
                float4 bb = br[i];
                float x, y, z, w_;
                unpack2(acc[2 * i], x, y); unpack2(acc[2 * i + 1], z, w_);
                x += bb.x; y += bb.y; z += bb.z; w_ += bb.w;
                asm volatile(
                    "red.global.add.v4.f32 [%0], {%1, %2, %3, %4};"
                    :: "l"(ar + 4 * i), "f"(x), "f"(y), "f"(z), "f"(w_)
                    : "memory");
            }
        }
    }
}

// ---------------------------------------------------------------------------
// H2 = lrelu([node_feats, agg] @ upd_w1 + ub1)
__global__ __launch_bounds__(256, 1) void upd1_kernel(
    const float* __restrict__ nf, const float* __restrict__ w1,
    const float* __restrict__ b1, int N)
{
    extern __shared__ char smraw[];
    float* sw   = (float*)smraw;      // 256*128 = 32768
    float* sin_ = sw + 32768;         // 64*257  = 16448
    int tid = threadIdx.x;
    int n0 = blockIdx.x * 64;

    for (int i = tid; i < 8192; i += 256)
        ((float4*)sw)[i] = ((const float4*)w1)[i];
    for (int i = tid; i < 64 * 32; i += 256) {
        int r = i >> 5, q = i & 31, gn = n0 + r;
        float4 v = (gn < N) ? ((const float4*)nf)[(size_t)gn * 32 + q]
                            : make_float4(0.f, 0.f, 0.f, 0.f);
        float4 u = (gn < N) ? ((const float4*)g_agg)[(size_t)gn * 32 + q]
                            : make_float4(0.f, 0.f, 0.f, 0.f);
        float* p = sin_ + r * 257 + q * 4;
        p[0] = v.x; p[1] = v.y; p[2] = v.z; p[3] = v.w;
        float* p2 = sin_ + r * 257 + 128 + q * 4;
        p2[0] = u.x; p2[1] = u.y; p2[2] = u.z; p2[3] = u.w;
    }
    __syncthreads();

    int n = tid & 63, c0 = (tid >> 6) * 32;
    ull acc[16];
#pragma unroll
    for (int i = 0; i < 16; i++) acc[i] = pack2(0.f, 0.f);
#pragma unroll 4
    for (int k = 0; k < 256; k++) {
        float a = sin_[n * 257 + k];
        ull a2 = pack2(a, a);
        u2p wr = (u2p)(sw + k * ND + c0);
#pragma unroll
        for (int i = 0; i < 8; i++) {
            ulonglong2 w = wr[i];
            fma2(acc[2 * i], a2, w.x);
            fma2(acc[2 * i + 1], a2, w.y);
        }
    }
    int gn = n0 + n;
    if (gn < N) {
        const float4* br = (const float4*)(b1 + c0);
        float4* hr = (float4*)(g_H2 + (size_t)gn * ND + c0);
#pragma unroll
        for (int i = 0; i < 8; i++) {
            float4 bb = br[i];
            float x, y, z, w_;
            unpack2(acc[2 * i], x, y); unpack2(acc[2 * i + 1], z, w_);
            hr[i] = make_float4(lrelu(x + bb.x), lrelu(y + bb.y),
                                lrelu(z + bb.z), lrelu(w_ + bb.w));
        }
    }
}

// ---------------------------------------------------------------------------
// out = H2 @ upd_w2 + ub2
__global__ __launch_bounds__(512, 1) void upd2_kernel(
    const float* __restrict__ w2, const float* __restrict__ b2,
    float* __restrict__ out, int N)
{
    extern __shared__ char smraw[];
    float* sw  = (float*)smraw;       // 128*128 = 16384
    float* sh2 = sw + 16384;          // 128*129 = 16512
    int tid = threadIdx.x;
    int n0 = blockIdx.x * 128;

    for (int i = tid; i < 4096; i += 512)
        ((float4*)sw)[i] = ((const float4*)w2)[i];
    for (int i = tid; i < 128 * 32; i += 512) {
        int r = i >> 5, q = i & 31, gn = n0 + r;
        float4 v = (gn < N) ? ((const float4*)g_H2)[(size_t)gn * 32 + q]
                            : make_float4(0.f, 0.f, 0.f, 0.f);
        float* p = sh2 + r * 129 + q * 4;
        p[0] = v.x; p[1] = v.y; p[2] = v.z; p[3] = v.w;
    }
    __syncthreads();

    int n = tid & 127, c0 = (tid >> 7) * 32;
    ull acc[16];
#pragma unroll
    for (int i = 0; i < 16; i++) acc[i] = pack2(0.f, 0.f);
#pragma unroll 4
    for (int k = 0; k < 128; k++) {
        float a = sh2[n * 129 + k];
        ull a2 = pack2(a, a);
        u2p wr = (u2p)(sw + k * ND + c0);
#pragma unroll
        for (int i = 0; i < 8; i++) {
            ulonglong2 w = wr[i];
            fma2(acc[2 * i], a2, w.x);
            fma2(acc[2 * i + 1], a2, w.y);
        }
    }
    int gn = n0 + n;
    if (gn < N) {
        const float4* br = (const float4*)(b2 + c0);
        float4* orow = (float4*)(out + (size_t)gn * ND + c0);
#pragma unroll
        for (int i = 0; i < 8; i++) {
            float4 bb = br[i];
            float x, y, z, w_;
            unpack2(acc[2 * i], x, y); unpack2(acc[2 * i + 1], z, w_);
            orow[i] = make_float4(x + bb.x, y + bb.y, z + bb.z, w_ + bb.w);
        }
    }
}

// ---------------------------------------------------------------------------
extern "C" void kernel_launch(void* const* d_in, const int* in_sizes, int n_in,
                              void* d_out, int out_size)
{
    const float* nf  = (const float*)d_in[0];
    const float* ef  = (const float*)d_in[1];
    const float* mw1 = (const float*)d_in[2];
    const float* mb1 = (const float*)d_in[3];
    const float* mw2 = (const float*)d_in[4];
    const float* mb2 = (const float*)d_in[5];
    const float* uw1 = (const float*)d_in[6];
    const float* ub1 = (const float*)d_in[7];
    const float* uw2 = (const float*)d_in[8];
    const float* ub2 = (const float*)d_in[9];
    const int* eidx  = (const int*)d_in[10];   // int32 (JAX x64 disabled)
    float* out = (float*)d_out;

    int N = in_sizes[0] / ND;
    int E = in_sizes[10] / 2;

    cudaFuncSetAttribute(p_kernel,    cudaFuncAttributeMaxDynamicSharedMemorySize, 98560);
    cudaFuncSetAttribute(edge_kernel, cudaFuncAttributeMaxDynamicSharedMemorySize, 199680);
    cudaFuncSetAttribute(upd1_kernel, cudaFuncAttributeMaxDynamicSharedMemorySize, 196864);
    cudaFuncSetAttribute(upd2_kernel, cudaFuncAttributeMaxDynamicSharedMemorySize, 131584);

    int n4 = (N * ND) / 4;
    zero_kernel<<<(n4 + 255) / 256, 256>>>(n4);
    p_kernel<<<(N + 63) / 64, 256, 98560>>>(nf, mw1, N);
    edge_kernel<<<(E + TE - 1) / TE, 512, 199680>>>(ef, mw1, mb1, mw2, mb2, eidx, N, E);
    upd1_kernel<<<(N + 63) / 64, 256, 196864>>>(nf, uw1, ub1, N);
    upd2_kernel<<<(N + 127) / 128, 512, 131584>>>(uw2, ub2, out, N);
}

// round 7
// speedup vs baseline: 1.0115x; 1.0115x over previous
#include <cuda_runtime.h>

#define ND 128
#define ED 64
#define TE 128
#define MAXN 50000

typedef unsigned long long ull;
typedef const ulonglong2* u2p;

// scratch (static device arrays: allocation-free).
// __align__(256): accessed as float4 / red.global.add.v4.f32 (need >=16B).
__device__ __align__(256) float g_P[MAXN * ND];    // node_feats @ msg_w1[:128]
__device__ __align__(256) float g_agg[MAXN * ND];  // scatter-add accumulator
__device__ __align__(256) float g_H2[MAXN * ND];   // update hidden

__device__ __forceinline__ ull pack2(float x, float y) {
    ull r; asm("mov.b64 %0, {%1, %2};" : "=l"(r) : "f"(x), "f"(y)); return r;
}
__device__ __forceinline__ void unpack2(ull v, float& x, float& y) {
    asm("mov.b64 {%0, %1}, %2;" : "=f"(x), "=f"(y) : "l"(v));
}
__device__ __forceinline__ void fma2(ull& acc, ull a, ull b) {
    asm("fma.rn.f32x2 %0, %1, %2, %0;" : "+l"(acc) : "l"(a), "l"(b));
}
__device__ __forceinline__ float lrelu(float x) { return x >= 0.f ? x : 0.2f * x; }

// ---------------------------------------------------------------------------
__global__ void zero_kernel(int n4) {
    int i = blockIdx.x * blockDim.x + threadIdx.x;
    if (i < n4) ((float4*)g_agg)[i] = make_float4(0.f, 0.f, 0.f, 0.f);
}

// ---------------------------------------------------------------------------
// P = node_feats @ msg_w1[0:128, :]   (no bias)
// 1024 thr: 128 rows x 8 col-groups of 16
__global__ __launch_bounds__(1024, 1) void p_kernel(
    const float* __restrict__ nf, const float* __restrict__ w1, int N)
{
    extern __shared__ char smraw[];
    float* sw   = (float*)smraw;      // 128*128 = 16384
    float* sin_ = sw + 16384;         // 128*129 = 16512
    int tid = threadIdx.x;
    int n0 = blockIdx.x * 128;

    for (int i = tid; i < 4096; i += 1024)
        ((float4*)sw)[i] = ((const float4*)w1)[i];
    for (int i = tid; i < 128 * 32; i += 1024) {
        int r = i >> 5, q = i & 31, gn = n0 + r;
        float4 v = (gn < N) ? ((const float4*)nf)[(size_t)gn * 32 + q]
                            : make_float4(0.f, 0.f, 0.f, 0.f);
        float* p = sin_ + r * 129 + q * 4;
        p[0] = v.x; p[1] = v.y; p[2] = v.z; p[3] = v.w;
    }
    __syncthreads();

    int n = tid & 127, c0 = (tid >> 7) * 16;
    ull acc[8];
#pragma unroll
    for (int i = 0; i < 8; i++) acc[i] = pack2(0.f, 0.f);
#pragma unroll 4
    for (int k = 0; k < 128; k++) {
        float a = sin_[n * 129 + k];
        ull a2 = pack2(a, a);
        u2p wr = (u2p)(sw + k * ND + c0);
#pragma unroll
        for (int i = 0; i < 4; i++) {
            ulonglong2 w = wr[i];
            fma2(acc[2 * i], a2, w.x);
            fma2(acc[2 * i + 1], a2, w.y);
        }
    }
    int gn = n0 + n;
    if (gn < N) {
        float4* pr = (float4*)(g_P + (size_t)gn * ND + c0);
#pragma unroll
        for (int i = 0; i < 4; i++) {
            float x, y, z, w_;
            unpack2(acc[2 * i], x, y); unpack2(acc[2 * i + 1], z, w_);
            pr[i] = make_float4(x, y, z, w_);
        }
    }
}

// ---------------------------------------------------------------------------
// Fused edge kernel (1024 thr: 128 edges x 8 col-groups of 16):
//   h = lrelu(P[dst] + edge_feats @ w1[128:192] + b1)
//   messages = h @ w2 + b2
//   atomic scatter-add into g_agg[src]
__global__ __launch_bounds__(1024, 1) void edge_kernel(
    const float* __restrict__ ef,
    const float* __restrict__ w1, const float* __restrict__ b1,
    const float* __restrict__ w2, const float* __restrict__ b2,
    const int* __restrict__ eidx,   // int32 (JAX x64-disabled)
    int N, int E)
{
    extern __shared__ char smraw[];
    float* sw1e = (float*)smraw;       // 64*128   = 8192 floats
    float* sw2  = sw1e + 8192;         // 128*128  = 16384
    float* sb1  = sw2 + 16384;         // 128
    float* sb2  = sb1 + 128;           // 128
    float* sef  = sb2 + 128;           // 128*65   = 8320
    float* sh   = sef + 8320;          // 128*129  = 16512
    int*   ssrc = (int*)(sh + 16512);  // 128
    int*   sdst = ssrc + 128;          // 128

    int tid = threadIdx.x;
    int e0 = blockIdx.x * TE;

    for (int i = tid; i < 2048; i += 1024)
        ((float4*)sw1e)[i] = ((const float4*)(w1 + 128 * ND))[i];
    for (int i = tid; i < 4096; i += 1024)
        ((float4*)sw2)[i] = ((const float4*)w2)[i];
    if (tid < 32)       ((float4*)sb1)[tid]      = ((const float4*)b1)[tid];
    else if (tid < 64)  ((float4*)sb2)[tid - 32] = ((const float4*)b2)[tid - 32];
    if (tid < TE) {
        int ge = e0 + tid;
        if (ge < E) {
            int s = eidx[ge];
            int d = eidx[E + ge];
            ssrc[tid] = ((unsigned)s < (unsigned)N) ? s : -1;
            sdst[tid] = ((unsigned)d < (unsigned)N) ? d : 0;
        } else { ssrc[tid] = -1; sdst[tid] = 0; }
    }
    for (int i = tid; i < TE * 16; i += 1024) {
        int r = i >> 4, q = i & 15, ge = e0 + r;
        float4 v = (ge < E) ? ((const float4*)ef)[(size_t)ge * 16 + q]
                            : make_float4(0.f, 0.f, 0.f, 0.f);
        float* p = sef + r * 65 + q * 4;
        p[0] = v.x; p[1] = v.y; p[2] = v.z; p[3] = v.w;
    }
    __syncthreads();

    int e = tid & (TE - 1), c0 = (tid >> 7) * 16;

    // phase A: edge-part GEMM (K=64) + P gather + bias + leaky -> sh
    ull acc[8];
#pragma unroll
    for (int i = 0; i < 8; i++) acc[i] = pack2(0.f, 0.f);
#pragma unroll 4
    for (int k = 0; k < ED; k++) {
        float a = sef[e * 65 + k];
        ull a2 = pack2(a, a);
        u2p wr = (u2p)(sw1e + k * ND + c0);
#pragma unroll
        for (int i = 0; i < 4; i++) {
            ulonglong2 w = wr[i];
            fma2(acc[2 * i], a2, w.x);
            fma2(acc[2 * i + 1], a2, w.y);
        }
    }
    {
        int d = sdst[e];
        const float4* pr = (const float4*)(g_P + (size_t)d * ND + c0);
        const float4* br = (const float4*)(sb1 + c0);
        float* hrow = sh + e * 129 + c0;
#pragma unroll
        for (int i = 0; i < 4; i++) {
            float4 p = pr[i];
            float4 bb = br[i];
            float x, y, z, w_;
            unpack2(acc[2 * i], x, y); unpack2(acc[2 * i + 1], z, w_);
            x = lrelu(x + p.x + bb.x);
            y = lrelu(y + p.y + bb.y);
            z = lrelu(z + p.z + bb.z);
            w_ = lrelu(w_ + p.w + bb.w);
            hrow[4 * i] = x; hrow[4 * i + 1] = y;
            hrow[4 * i + 2] = z; hrow[4 * i + 3] = w_;
        }
    }
    __syncthreads();

    // phase B: messages = h @ w2 + b2, scatter-add
#pragma unroll
    for (int i = 0; i < 8; i++) acc[i] = pack2(0.f, 0.f);
#pragma unroll 4
    for (int k = 0; k < ND; k++) {
        float a = sh[e * 129 + k];
        ull a2 = pack2(a, a);
        u2p wr = (u2p)(sw2 + k * ND + c0);
#pragma unroll
        for (int i = 0; i < 4; i++) {
            ulonglong2 w = wr[i];
            fma2(acc[2 * i], a2, w.x);
            fma2(acc[2 * i + 1], a2, w.y);
        }
    }
    {
        int s = ssrc[e];
        if (s >= 0) {
            const float4* br = (const float4*)(sb2 + c0);
            float* ar = g_agg + (size_t)s * ND + c0;
#pragma unroll
            for (int i = 0; i < 4; i++) {
                float4 bb = br[i];
                float x, y, z, w_;
                unpack2(acc[2 * i], x, y); unpack2(acc[2 * i + 1], z, w_);
                x += bb.x; y += bb.y; z += bb.z; w_ += bb.w;
                asm volatile(
                    "red.global.add.v4.f32 [%0], {%1, %2, %3, %4};"
                    :: "l"(ar + 4 * i), "f"(x), "f"(y), "f"(z), "f"(w_)
                    : "memory");
            }
        }
    }
}

// ---------------------------------------------------------------------------
// H2 = lrelu([node_feats, agg] @ upd_w1 + ub1)
// 1024 thr: 64 rows x 16 col-groups of 8
__global__ __launch_bounds__(1024, 1) void upd1_kernel(
    const float* __restrict__ nf, const float* __restrict__ w1,
    const float* __restrict__ b1, int N)
{
    extern __shared__ char smraw[];
    float* sw   = (float*)smraw;      // 256*128 = 32768
    float* sin_ = sw + 32768;         // 64*257  = 16448
    int tid = threadIdx.x;
    int n0 = blockIdx.x * 64;

    for (int i = tid; i < 8192; i += 1024)
        ((float4*)sw)[i] = ((const float4*)w1)[i];
    for (int i = tid; i < 64 * 32; i += 1024) {
        int r = i >> 5, q = i & 31, gn = n0 + r;
        float4 v = (gn < N) ? ((const float4*)nf)[(size_t)gn * 32 + q]
                            : make_float4(0.f, 0.f, 0.f, 0.f);
        float4 u = (gn < N) ? ((const float4*)g_agg)[(size_t)gn * 32 + q]
                            : make_float4(0.f, 0.f, 0.f, 0.f);
        float* p = sin_ + r * 257 + q * 4;
        p[0] = v.x; p[1] = v.y; p[2] = v.z; p[3] = v.w;
        float* p2 = sin_ + r * 257 + 128 + q * 4;
        p2[0] = u.x; p2[1] = u.y; p2[2] = u.z; p2[3] = u.w;
    }
    __syncthreads();

    int n = tid & 63, c0 = (tid >> 6) * 8;
    ull acc[4];
#pragma unroll
    for (int i = 0; i < 4; i++) acc[i] = pack2(0.f, 0.f);
#pragma unroll 4
    for (int k = 0; k < 256; k++) {
        float a = sin_[n * 257 + k];
        ull a2 = pack2(a, a);
        u2p wr = (u2p)(sw + k * ND + c0);
#pragma unroll
        for (int i = 0; i < 2; i++) {
            ulonglong2 w = wr[i];
            fma2(acc[2 * i], a2, w.x);
            fma2(acc[2 * i + 1], a2, w.y);
        }
    }
    int gn = n0 + n;
    if (gn < N) {
        const float4* br = (const float4*)(b1 + c0);
        float4* hr = (float4*)(g_H2 + (size_t)gn * ND + c0);
#pragma unroll
        for (int i = 0; i < 2; i++) {
            float4 bb = br[i];
            float x, y, z, w_;
            unpack2(acc[2 * i], x, y); unpack2(acc[2 * i + 1], z, w_);
            hr[i] = make_float4(lrelu(x + bb.x), lrelu(y + bb.y),
                                lrelu(z + bb.z), lrelu(w_ + bb.w));
        }
    }
}

// ---------------------------------------------------------------------------
// out = H2 @ upd_w2 + ub2    (1024 thr: 128 rows x 8 col-groups of 16)
__global__ __launch_bounds__(1024, 1) void upd2_kernel(
    const float* __restrict__ w2, const float* __restrict__ b2,
    float* __restrict__ out, int N)
{
    extern __shared__ char smraw[];
    float* sw  = (float*)smraw;       // 128*128 = 16384
    float* sh2 = sw + 16384;          // 128*129 = 16512
    int tid = threadIdx.x;
    int n0 = blockIdx.x * 128;

    for (int i = tid; i < 4096; i += 1024)
        ((float4*)sw)[i] = ((const float4*)w2)[i];
    for (int i = tid; i < 128 * 32; i += 1024) {
        int r = i >> 5, q = i & 31, gn = n0 + r;
        float4 v = (gn < N) ? ((const float4*)g_H2)[(size_t)gn * 32 + q]
                            : make_float4(0.f, 0.f, 0.f, 0.f);
        float* p = sh2 + r * 129 + q * 4;
        p[0] = v.x; p[1] = v.y; p[2] = v.z; p[3] = v.w;
    }
    __syncthreads();

    int n = tid & 127, c0 = (tid >> 7) * 16;
    ull acc[8];
#pragma unroll
    for (int i = 0; i < 8; i++) acc[i] = pack2(0.f, 0.f);
#pragma unroll 4
    for (int k = 0; k < 128; k++) {
        float a = sh2[n * 129 + k];
        ull a2 = pack2(a, a);
        u2p wr = (u2p)(sw + k * ND + c0);
#pragma unroll
        for (int i = 0; i < 4; i++) {
            ulonglong2 w = wr[i];
            fma2(acc[2 * i], a2, w.x);
            fma2(acc[2 * i + 1], a2, w.y);
        }
    }
    int gn = n0 + n;
    if (gn < N) {
        const float4* br = (const float4*)(b2 + c0);
        float4* orow = (float4*)(out + (size_t)gn * ND + c0);
#pragma unroll
        for (int i = 0; i < 4; i++) {
            float4 bb = br[i];
            float x, y, z, w_;
            unpack2(acc[2 * i], x, y); unpack2(acc[2 * i + 1], z, w_);
            orow[i] = make_float4(x + bb.x, y + bb.y, z + bb.z, w_ + bb.w);
        }
    }
}

// ---------------------------------------------------------------------------
extern "C" void kernel_launch(void* const* d_in, const int* in_sizes, int n_in,
                              void* d_out, int out_size)
{
    const float* nf  = (const float*)d_in[0];
    const float* ef  = (const float*)d_in[1];
    const float* mw1 = (const float*)d_in[2];
    const float* mb1 = (const float*)d_in[3];
    const float* mw2 = (const float*)d_in[4];
    const float* mb2 = (const float*)d_in[5];
    const float* uw1 = (const float*)d_in[6];
    const float* ub1 = (const float*)d_in[7];
    const float* uw2 = (const float*)d_in[8];
    const float* ub2 = (const float*)d_in[9];
    const int* eidx  = (const int*)d_in[10];   // int32 (JAX x64 disabled)
    float* out = (float*)d_out;

    int N = in_sizes[0] / ND;
    int E = in_sizes[10] / 2;

    cudaFuncSetAttribute(p_kernel,    cudaFuncAttributeMaxDynamicSharedMemorySize, 131584);
    cudaFuncSetAttribute(edge_kernel, cudaFuncAttributeMaxDynamicSharedMemorySize, 199680);
    cudaFuncSetAttribute(upd1_kernel, cudaFuncAttributeMaxDynamicSharedMemorySize, 196864);
    cudaFuncSetAttribute(upd2_kernel, cudaFuncAttributeMaxDynamicSharedMemorySize, 131584);

    int n4 = (N * ND) / 4;
    zero_kernel<<<(n4 + 255) / 256, 256>>>(n4);
    p_kernel<<<(N + 127) / 128, 1024, 131584>>>(nf, mw1, N);
    edge_kernel<<<(E + TE - 1) / TE, 1024, 199680>>>(ef, mw1, mb1, mw2, mb2, eidx, N, E);
    upd1_kernel<<<(N + 63) / 64, 1024, 196864>>>(nf, uw1, ub1, N);
    upd2_kernel<<<(N + 127) / 128, 1024, 131584>>>(uw2, ub2, out, N);
}

// round 9
// speedup vs baseline: 1.2887x; 1.2740x over previous
#include <cuda_runtime.h>

#define ND 128
#define TE 128
#define MAXN 50000

typedef unsigned long long ull;
typedef const ulonglong2* u2p;

__device__ __align__(256) float g_P[MAXN * ND];
__device__ __align__(256) float g_agg[MAXN * ND];
__device__ __align__(256) float g_H2[MAXN * ND];

__device__ __forceinline__ ull pack2(float x, float y) {
    ull r; asm("mov.b64 %0, {%1, %2};" : "=l"(r) : "f"(x), "f"(y)); return r;
}
__device__ __forceinline__ void unpack2(ull v, float& x, float& y) {
    asm("mov.b64 {%0, %1}, %2;" : "=f"(x), "=f"(y) : "l"(v));
}
__device__ __forceinline__ void fma2(ull& acc, ull a, ull b) {
    asm("fma.rn.f32x2 %0, %1, %2, %0;" : "+l"(acc) : "l"(a), "l"(b));
}
__device__ __forceinline__ float lrelu(float x) { return x >= 0.f ? x : 0.2f * x; }

// 8 fma2 on one 16-col group with one broadcast activation pair
__device__ __forceinline__ void fma_row16(ull* acc, ull a2, const float* wrow) {
    u2p wr = (u2p)wrow;
    ulonglong2 w0 = wr[0], w1 = wr[1], w2 = wr[2], w3 = wr[3];
    fma2(acc[0], a2, w0.x); fma2(acc[1], a2, w0.y);
    fma2(acc[2], a2, w1.x); fma2(acc[3], a2, w1.y);
    fma2(acc[4], a2, w2.x); fma2(acc[5], a2, w2.y);
    fma2(acc[6], a2, w3.x); fma2(acc[7], a2, w3.y);
}

// ---------------------------------------------------------------------------
__global__ void zero_kernel(int n4) {
    int i = blockIdx.x * blockDim.x + threadIdx.x;
    if (i < n4) ((float4*)g_agg)[i] = make_float4(0.f, 0.f, 0.f, 0.f);
}

// ---------------------------------------------------------------------------
// P = node_feats @ msg_w1[0:128,:]. 128 rows/block, 256 thr (thread: 4 rows x 16 cols)
__global__ __launch_bounds__(256, 1) void p_kernel(
    const float* __restrict__ nf, const float* __restrict__ w1, int N)
{
    extern __shared__ float sm[];
    float* sw = sm;          // 128*128
    float* sa = sm + 16384;  // 128 k * 132 (k-major, transposed)
    int tid = threadIdx.x;
    int n0 = blockIdx.x * 128;

    for (int i = tid; i < 4096; i += 256)
        ((float4*)sw)[i] = ((const float4*)w1)[i];
    for (int i = tid; i < 4096; i += 256) {
        int r = i & 127, j = i >> 7, gn = n0 + r;
        float4 v = (gn < N) ? ((const float4*)nf)[(size_t)gn * 32 + j]
                            : make_float4(0.f, 0.f, 0.f, 0.f);
        sa[(4 * j + 0) * 132 + r] = v.x;
        sa[(4 * j + 1) * 132 + r] = v.y;
        sa[(4 * j + 2) * 132 + r] = v.z;
        sa[(4 * j + 3) * 132 + r] = v.w;
    }
    __syncthreads();

    int q = tid & 31, c0 = (tid >> 5) * 16, rb = 4 * q;
    ull acc[32];
#pragma unroll
    for (int i = 0; i < 32; i++) acc[i] = pack2(0.f, 0.f);
#pragma unroll 2
    for (int k = 0; k < 128; k++) {
        float4 a = *(float4*)(sa + k * 132 + rb);
        const float* wrow = sw + k * ND + c0;
        fma_row16(acc + 0,  pack2(a.x, a.x), wrow);
        fma_row16(acc + 8,  pack2(a.y, a.y), wrow);
        fma_row16(acc + 16, pack2(a.z, a.z), wrow);
        fma_row16(acc + 24, pack2(a.w, a.w), wrow);
    }
#pragma unroll
    for (int j = 0; j < 4; j++) {
        int gn = n0 + rb + j;
        if (gn < N) {
            float4* pr = (float4*)(g_P + (size_t)gn * ND + c0);
#pragma unroll
            for (int i = 0; i < 4; i++) {
                float x, y, z, w_;
                unpack2(acc[j * 8 + 2 * i], x, y);
                unpack2(acc[j * 8 + 2 * i + 1], z, w_);
                pr[i] = make_float4(x, y, z, w_);
            }
        }
    }
}

// ---------------------------------------------------------------------------
// Fused edge kernel. 128 edges/block, 256 thr (thread: 4 edges x 16 cols).
__global__ __launch_bounds__(256, 1) void edge_kernel(
    const float* __restrict__ ef,
    const float* __restrict__ w1, const float* __restrict__ b1,
    const float* __restrict__ w2, const float* __restrict__ b2,
    const int* __restrict__ eidx, int N, int E)
{
    extern __shared__ float sm[];
    float* sw1e = sm;                 // 64*128   = 8192
    float* sw2  = sm + 8192;          // 128*128  = 16384
    float* sb1  = sm + 24576;         // 128
    float* sb2  = sm + 24704;         // 128
    float* seft = sm + 24832;         // 64 k * 132 = 8448  (k-major)
    float* sht  = sm + 33280;         // 128 k * 132 = 16896 (k-major)
    int*   ssrc = (int*)(sm + 50176); // 128
    int*   sdst = ssrc + 128;         // 128

    int tid = threadIdx.x;
    int e0 = blockIdx.x * TE;

    for (int i = tid; i < 2048; i += 256)
        ((float4*)sw1e)[i] = ((const float4*)(w1 + 128 * ND))[i];
    for (int i = tid; i < 4096; i += 256)
        ((float4*)sw2)[i] = ((const float4*)w2)[i];
    if (tid < 32)       ((float4*)sb1)[tid]      = ((const float4*)b1)[tid];
    else if (tid < 64)  ((float4*)sb2)[tid - 32] = ((const float4*)b2)[tid - 32];
    if (tid < TE) {
        int ge = e0 + tid;
        if (ge < E) {
            int s = eidx[ge], d = eidx[E + ge];
            ssrc[tid] = ((unsigned)s < (unsigned)N) ? s : -1;
            sdst[tid] = ((unsigned)d < (unsigned)N) ? d : 0;
        } else { ssrc[tid] = -1; sdst[tid] = 0; }
    }
    for (int i = tid; i < 2048; i += 256) {
        int r = i & 127, j = i >> 7, ge = e0 + r;
        float4 v = (ge < E) ? ((const float4*)ef)[(size_t)ge * 16 + j]
                            : make_float4(0.f, 0.f, 0.f, 0.f);
        seft[(4 * j + 0) * 132 + r] = v.x;
        seft[(4 * j + 1) * 132 + r] = v.y;
        seft[(4 * j + 2) * 132 + r] = v.z;
        seft[(4 * j + 3) * 132 + r] = v.w;
    }
    __syncthreads();

    int q = tid & 31, c0 = (tid >> 5) * 16, eb = 4 * q;

    // phase A: h = lrelu(P[dst] + ef @ w1e + b1), K=64
    ull acc[32];
#pragma unroll
    for (int i = 0; i < 32; i++) acc[i] = pack2(0.f, 0.f);
#pragma unroll 2
    for (int k = 0; k < 64; k++) {
        float4 a = *(float4*)(seft + k * 132 + eb);
        const float* wrow = sw1e + k * ND + c0;
        fma_row16(acc + 0,  pack2(a.x, a.x), wrow);
        fma_row16(acc + 8,  pack2(a.y, a.y), wrow);
        fma_row16(acc + 16, pack2(a.z, a.z), wrow);
        fma_row16(acc + 24, pack2(a.w, a.w), wrow);
    }
    float hh[4][16];
#pragma unroll
    for (int j = 0; j < 4; j++) {
        int d = sdst[eb + j];
        const float4* pr = (const float4*)(g_P + (size_t)d * ND + c0);
        const float4* br = (const float4*)(sb1 + c0);
#pragma unroll
        for (int i = 0; i < 4; i++) {
            float4 p = pr[i], bb = br[i];
            float x, y, z, w_;
            unpack2(acc[j * 8 + 2 * i], x, y);
            unpack2(acc[j * 8 + 2 * i + 1], z, w_);
            hh[j][4 * i + 0] = lrelu(x + p.x + bb.x);
            hh[j][4 * i + 1] = lrelu(y + p.y + bb.y);
            hh[j][4 * i + 2] = lrelu(z + p.z + bb.z);
            hh[j][4 * i + 3] = lrelu(w_ + p.w + bb.w);
        }
    }
    // transposed store: sht[c][edge], 4 edges per float4
#pragma unroll
    for (int c = 0; c < 16; c++)
        *(float4*)(sht + (c0 + c) * 132 + eb) =
            make_float4(hh[0][c], hh[1][c], hh[2][c], hh[3][c]);
    __syncthreads();

    // phase B: messages = h @ w2 + b2, K=128, scatter
#pragma unroll
    for (int i = 0; i < 32; i++) acc[i] = pack2(0.f, 0.f);
#pragma unroll 2
    for (int k = 0; k < 128; k++) {
        float4 a = *(float4*)(sht + k * 132 + eb);
        const float* wrow = sw2 + k * ND + c0;
        fma_row16(acc + 0,  pack2(a.x, a.x), wrow);
        fma_row16(acc + 8,  pack2(a.y, a.y), wrow);
        fma_row16(acc + 16, pack2(a.z, a.z), wrow);
        fma_row16(acc + 24, pack2(a.w, a.w), wrow);
    }
#pragma unroll
    for (int j = 0; j < 4; j++) {
        int s = ssrc[eb + j];
        if (s >= 0) {
            const float4* br = (const float4*)(sb2 + c0);
            float* ar = g_agg + (size_t)s * ND + c0;
#pragma unroll
            for (int i = 0; i < 4; i++) {
                float4 bb = br[i];
                float x, y, z, w_;
                unpack2(acc[j * 8 + 2 * i], x, y);
                unpack2(acc[j * 8 + 2 * i + 1], z, w_);
                x += bb.x; y += bb.y; z += bb.z; w_ += bb.w;
                asm volatile(
                    "red.global.add.v4.f32 [%0], {%1, %2, %3, %4};"
                    :: "l"(ar + 4 * i), "f"(x), "f"(y), "f"(z), "f"(w_)
                    : "memory");
            }
        }
    }
}

// ---------------------------------------------------------------------------
// H2 = lrelu([nf, agg] @ upd_w1 + ub1). 64 rows/block, 256 thr (2 rows x 16 cols)
__global__ __launch_bounds__(256, 1) void upd1_kernel(
    const float* __restrict__ nf, const float* __restrict__ w1,
    const float* __restrict__ b1, int N)
{
    extern __shared__ float sm[];
    float* sw = sm;          // 256*128 = 32768
    float* sa = sm + 32768;  // 256 k * 68 = 17408
    int tid = threadIdx.x;
    int n0 = blockIdx.x * 64;

    for (int i = tid; i < 8192; i += 256)
        ((float4*)sw)[i] = ((const float4*)w1)[i];
    for (int i = tid; i < 2048; i += 256) {
        int r = i & 63, j = i >> 6, gn = n0 + r;
        float4 v = (gn < N) ? ((const float4*)nf)[(size_t)gn * 32 + j]
                            : make_float4(0.f, 0.f, 0.f, 0.f);
        float4 u = (gn < N) ? ((const float4*)g_agg)[(size_t)gn * 32 + j]
                            : make_float4(0.f, 0.f, 0.f, 0.f);
        sa[(4 * j + 0) * 68 + r] = v.x;
        sa[(4 * j + 1) * 68 + r] = v.y;
        sa[(4 * j + 2) * 68 + r] = v.z;
        sa[(4 * j + 3) * 68 + r] = v.w;
        sa[(128 + 4 * j + 0) * 68 + r] = u.x;
        sa[(128 + 4 * j + 1) * 68 + r] = u.y;
        sa[(128 + 4 * j + 2) * 68 + r] = u.z;
        sa[(128 + 4 * j + 3) * 68 + r] = u.w;
    }
    __syncthreads();

    int q = tid & 31, c0 = (tid >> 5) * 16, rb = 2 * q;
    ull acc[16];
#pragma unroll
    for (int i = 0; i < 16; i++) acc[i] = pack2(0.f, 0.f);
#pragma unroll 2
    for (int k = 0; k < 256; k++) {
        float2 a = *(float2*)(sa + k * 68 + rb);
        const float* wrow = sw + k * ND + c0;
        fma_row16(acc + 0, pack2(a.x, a.x), wrow);
        fma_row16(acc + 8, pack2(a.y, a.y), wrow);
    }
#pragma unroll
    for (int j = 0; j < 2; j++) {
        int gn = n0 + rb + j;
        if (gn < N) {
            const float4* br = (const float4*)(b1 + c0);
            float4* hr = (float4*)(g_H2 + (size_t)gn * ND + c0);
#pragma unroll
            for (int i = 0; i < 4; i++) {
                float4 bb = br[i];
                float x, y, z, w_;
                unpack2(acc[j * 8 + 2 * i], x, y);
                unpack2(acc[j * 8 + 2 * i + 1], z, w_);
                hr[i] = make_float4(lrelu(x + bb.x), lrelu(y + bb.y),
                                    lrelu(z + bb.z), lrelu(w_ + bb.w));
            }
        }
    }
}

// ---------------------------------------------------------------------------
// out = H2 @ upd_w2 + ub2. 128 rows/block, 256 thr (4 rows x 16 cols)
__global__ __launch_bounds__(256, 1) void upd2_kernel(
    const float* __restrict__ w2, const float* __restrict__ b2,
    float* __restrict__ out, int N)
{
    extern __shared__ float sm[];
    float* sw = sm;          // 128*128
    float* sa = sm + 16384;  // 128 k * 132
    int tid = threadIdx.x;
    int n0 = blockIdx.x * 128;

    for (int i = tid; i < 4096; i += 256)
        ((float4*)sw)[i] = ((const float4*)w2)[i];
    for (int i = tid; i < 4096; i += 256) {
        int r = i & 127, j = i >> 7, gn = n0 + r;
        float4 v = (gn < N) ? ((const float4*)g_H2)[(size_t)gn * 32 + j]
                            : make_float4(0.f, 0.f, 0.f, 0.f);
        sa[(4 * j + 0) * 132 + r] = v.x;
        sa[(4 * j + 1) * 132 + r] = v.y;
        sa[(4 * j + 2) * 132 + r] = v.z;
        sa[(4 * j + 3) * 132 + r] = v.w;
    }
    __syncthreads();

    int q = tid & 31, c0 = (tid >> 5) * 16, rb = 4 * q;
    ull acc[32];
#pragma unroll
    for (int i = 0; i < 32; i++) acc[i] = pack2(0.f, 0.f);
#pragma unroll 2
    for (int k = 0; k < 128; k++) {
        float4 a = *(float4*)(sa + k * 132 + rb);
        const float* wrow = sw + k * ND + c0;
        fma_row16(acc + 0,  pack2(a.x, a.x), wrow);
        fma_row16(acc + 8,  pack2(a.y, a.y), wrow);
        fma_row16(acc + 16, pack2(a.z, a.z), wrow);
        fma_row16(acc + 24, pack2(a.w, a.w), wrow);
    }
#pragma unroll
    for (int j = 0; j < 4; j++) {
        int gn = n0 + rb + j;
        if (gn < N) {
            const float4* br = (const float4*)(b2 + c0);
            float4* orow = (float4*)(out + (size_t)gn * ND + c0);
#pragma unroll
            for (int i = 0; i < 4; i++) {
                float4 bb = br[i];
                float x, y, z, w_;
                unpack2(acc[j * 8 + 2 * i], x, y);
                unpack2(acc[j * 8 + 2 * i + 1], z, w_);
                orow[i] = make_float4(x + bb.x, y + bb.y, z + bb.z, w_ + bb.w);
            }
        }
    }
}

// ---------------------------------------------------------------------------
extern "C" void kernel_launch(void* const* d_in, const int* in_sizes, int n_in,
                              void* d_out, int out_size)
{
    const float* nf  = (const float*)d_in[0];
    const float* ef  = (const float*)d_in[1];
    const float* mw1 = (const float*)d_in[2];
    const float* mb1 = (const float*)d_in[3];
    const float* mw2 = (const float*)d_in[4];
    const float* mb2 = (const float*)d_in[5];
    const float* uw1 = (const float*)d_in[6];
    const float* ub1 = (const float*)d_in[7];
    const float* uw2 = (const float*)d_in[8];
    const float* ub2 = (const float*)d_in[9];
    const int* eidx  = (const int*)d_in[10];   // int32 (JAX x64 disabled)
    float* out = (float*)d_out;

    int N = in_sizes[0] / ND;
    int E = in_sizes[10] / 2;

    const int P_SM  = (16384 + 128 * 132) * 4;            // 133120
    const int E_SM  = (50176 + 256) * 4;                  // 201728
    const int U1_SM = (32768 + 256 * 68) * 4;             // 200704
    const int U2_SM = (16384 + 128 * 132) * 4;            // 133120

    cudaFuncSetAttribute(p_kernel,    cudaFuncAttributeMaxDynamicSharedMemorySize, P_SM);
    cudaFuncSetAttribute(edge_kernel, cudaFuncAttributeMaxDynamicSharedMemorySize, E_SM);
    cudaFuncSetAttribute(upd1_kernel, cudaFuncAttributeMaxDynamicSharedMemorySize, U1_SM);
    cudaFuncSetAttribute(upd2_kernel, cudaFuncAttributeMaxDynamicSharedMemorySize, U2_SM);

    int n4 = (N * ND) / 4;
    zero_kernel<<<(n4 + 255) / 256, 256>>>(n4);
    p_kernel<<<(N + 127) / 128, 256, P_SM>>>(nf, mw1, N);
    edge_kernel<<<(E + TE - 1) / TE, 256, E_SM>>>(ef, mw1, mb1, mw2, mb2, eidx, N, E);
    upd1_kernel<<<(N + 63) / 64, 256, U1_SM>>>(nf, uw1, ub1, N);
    upd2_kernel<<<(N + 127) / 128, 256, U2_SM>>>(uw2, ub2, out, N);
}

// round 11
// speedup vs baseline: 1.3913x; 1.0796x over previous
#include <cuda_runtime.h>

#define ND 128
#define TE 128
#define MAXN 50000

typedef unsigned long long ull;
typedef const ulonglong2* u2p;

__device__ __align__(256) float g_P[MAXN * ND];
__device__ __align__(256) float g_agg[MAXN * ND];
__device__ __align__(256) float g_H2[MAXN * ND];

__device__ __forceinline__ ull pack2(float x, float y) {
    ull r; asm("mov.b64 %0, {%1, %2};" : "=l"(r) : "f"(x), "f"(y)); return r;
}
__device__ __forceinline__ void unpack2(ull v, float& x, float& y) {
    asm("mov.b64 {%0, %1}, %2;" : "=f"(x), "=f"(y) : "l"(v));
}
__device__ __forceinline__ void fma2(ull& acc, ull a, ull b) {
    asm("fma.rn.f32x2 %0, %1, %2, %0;" : "+l"(acc) : "l"(a), "l"(b));
}
__device__ __forceinline__ float lrelu(float x) { return x >= 0.f ? x : 0.2f * x; }

// 4 fma2 on one 8-col group with one broadcast activation pair
__device__ __forceinline__ void fma_row8(ull* acc, ull a2, const float* wrow) {
    u2p wr = (u2p)wrow;
    ulonglong2 w0 = wr[0], w1 = wr[1];
    fma2(acc[0], a2, w0.x); fma2(acc[1], a2, w0.y);
    fma2(acc[2], a2, w1.x); fma2(acc[3], a2, w1.y);
}

// ---------------------------------------------------------------------------
__global__ void zero_kernel(int n4) {
    int i = blockIdx.x * blockDim.x + threadIdx.x;
    if (i < n4) ((float4*)g_agg)[i] = make_float4(0.f, 0.f, 0.f, 0.f);
}

// ---------------------------------------------------------------------------
// P = node_feats @ msg_w1[0:128,:]. 128 rows/block, 512 thr (4 rows x 8 cols)
__global__ __launch_bounds__(512, 1) void p_kernel(
    const float* __restrict__ nf, const float* __restrict__ w1, int N)
{
    extern __shared__ float sm[];
    float* sw = sm;          // 128*128
    float* sa = sm + 16384;  // 128 k * 132 (k-major)
    int tid = threadIdx.x;
    int n0 = blockIdx.x * 128;

    for (int i = tid; i < 4096; i += 512)
        ((float4*)sw)[i] = ((const float4*)w1)[i];
    for (int i = tid; i < 4096; i += 512) {
        int r = i & 127, j = i >> 7, gn = n0 + r;
        float4 v = (gn < N) ? ((const float4*)nf)[(size_t)gn * 32 + j]
                            : make_float4(0.f, 0.f, 0.f, 0.f);
        sa[(4 * j + 0) * 132 + r] = v.x;
        sa[(4 * j + 1) * 132 + r] = v.y;
        sa[(4 * j + 2) * 132 + r] = v.z;
        sa[(4 * j + 3) * 132 + r] = v.w;
    }
    __syncthreads();

    int q = tid & 31, c0 = (tid >> 5) * 8, rb = 4 * q;
    ull acc[16];
#pragma unroll
    for (int i = 0; i < 16; i++) acc[i] = pack2(0.f, 0.f);
#pragma unroll 2
    for (int k = 0; k < 128; k++) {
        float4 a = *(float4*)(sa + k * 132 + rb);
        const float* wrow = sw + k * ND + c0;
        fma_row8(acc + 0,  pack2(a.x, a.x), wrow);
        fma_row8(acc + 4,  pack2(a.y, a.y), wrow);
        fma_row8(acc + 8,  pack2(a.z, a.z), wrow);
        fma_row8(acc + 12, pack2(a.w, a.w), wrow);
    }
#pragma unroll
    for (int j = 0; j < 4; j++) {
        int gn = n0 + rb + j;
        if (gn < N) {
            float4* pr = (float4*)(g_P + (size_t)gn * ND + c0);
#pragma unroll
            for (int i = 0; i < 2; i++) {
                float x, y, z, w_;
                unpack2(acc[j * 4 + 2 * i], x, y);
                unpack2(acc[j * 4 + 2 * i + 1], z, w_);
                pr[i] = make_float4(x, y, z, w_);
            }
        }
    }
}

// ---------------------------------------------------------------------------
// Fused edge kernel. 128 edges/block, 512 thr (4 edges x 8 cols).
__global__ __launch_bounds__(512, 1) void edge_kernel(
    const float* __restrict__ ef,
    const float* __restrict__ w1, const float* __restrict__ b1,
    const float* __restrict__ w2, const float* __restrict__ b2,
    const int* __restrict__ eidx, int N, int E)
{
    extern __shared__ float sm[];
    float* sw1e = sm;                 // 64*128   = 8192
    float* sw2  = sm + 8192;          // 128*128  = 16384
    float* sb1  = sm + 24576;         // 128
    float* sb2  = sm + 24704;         // 128
    float* seft = sm + 24832;         // 64 k * 132 = 8448  (k-major)
    float* sht  = sm + 33280;         // 128 k * 132 = 16896 (k-major)
    int*   ssrc = (int*)(sm + 50176); // 128
    int*   sdst = ssrc + 128;         // 128

    int tid = threadIdx.x;
    int e0 = blockIdx.x * TE;

    for (int i = tid; i < 2048; i += 512)
        ((float4*)sw1e)[i] = ((const float4*)(w1 + 128 * ND))[i];
    for (int i = tid; i < 4096; i += 512)
        ((float4*)sw2)[i] = ((const float4*)w2)[i];
    if (tid < 32)       ((float4*)sb1)[tid]      = ((const float4*)b1)[tid];
    else if (tid < 64)  ((float4*)sb2)[tid - 32] = ((const float4*)b2)[tid - 32];
    if (tid < TE) {
        int ge = e0 + tid;
        if (ge < E) {
            int s = eidx[ge], d = eidx[E + ge];
            ssrc[tid] = ((unsigned)s < (unsigned)N) ? s : -1;
            sdst[tid] = ((unsigned)d < (unsigned)N) ? d : 0;
        } else { ssrc[tid] = -1; sdst[tid] = 0; }
    }
    for (int i = tid; i < 2048; i += 512) {
        int r = i & 127, j = i >> 7, ge = e0 + r;
        float4 v = (ge < E) ? ((const float4*)ef)[(size_t)ge * 16 + j]
                            : make_float4(0.f, 0.f, 0.f, 0.f);
        seft[(4 * j + 0) * 132 + r] = v.x;
        seft[(4 * j + 1) * 132 + r] = v.y;
        seft[(4 * j + 2) * 132 + r] = v.z;
        seft[(4 * j + 3) * 132 + r] = v.w;
    }
    __syncthreads();

    int q = tid & 31, c0 = (tid >> 5) * 8, eb = 4 * q;

    // phase A: h = lrelu(P[dst] + ef @ w1e + b1), K=64
    ull acc[16];
#pragma unroll
    for (int i = 0; i < 16; i++) acc[i] = pack2(0.f, 0.f);
#pragma unroll 2
    for (int k = 0; k < 64; k++) {
        float4 a = *(float4*)(seft + k * 132 + eb);
        const float* wrow = sw1e + k * ND + c0;
        fma_row8(acc + 0,  pack2(a.x, a.x), wrow);
        fma_row8(acc + 4,  pack2(a.y, a.y), wrow);
        fma_row8(acc + 8,  pack2(a.z, a.z), wrow);
        fma_row8(acc + 12, pack2(a.w, a.w), wrow);
    }
    float hh[4][8];
#pragma unroll
    for (int j = 0; j < 4; j++) {
        int d = sdst[eb + j];
        const float4* pr = (const float4*)(g_P + (size_t)d * ND + c0);
        const float4* br = (const float4*)(sb1 + c0);
#pragma unroll
        for (int i = 0; i < 2; i++) {
            float4 p = pr[i], bb = br[i];
            float x, y, z, w_;
            unpack2(acc[j * 4 + 2 * i], x, y);
            unpack2(acc[j * 4 + 2 * i + 1], z, w_);
            hh[j][4 * i + 0] = lrelu(x + p.x + bb.x);
            hh[j][4 * i + 1] = lrelu(y + p.y + bb.y);
            hh[j][4 * i + 2] = lrelu(z + p.z + bb.z);
            hh[j][4 * i + 3] = lrelu(w_ + p.w + bb.w);
        }
    }
    // transposed store: sht[c][edge], 4 edges per float4
#pragma unroll
    for (int c = 0; c < 8; c++)
        *(float4*)(sht + (c0 + c) * 132 + eb) =
            make_float4(hh[0][c], hh[1][c], hh[2][c], hh[3][c]);
    __syncthreads();

    // phase B: messages = h @ w2 + b2, K=128, scatter
#pragma unroll
    for (int i = 0; i < 16; i++) acc[i] = pack2(0.f, 0.f);
#pragma unroll 2
    for (int k = 0; k < 128; k++) {
        float4 a = *(float4*)(sht + k * 132 + eb);
        const float* wrow = sw2 + k * ND + c0;
        fma_row8(acc + 0,  pack2(a.x, a.x), wrow);
        fma_row8(acc + 4,  pack2(a.y, a.y), wrow);
        fma_row8(acc + 8,  pack2(a.z, a.z), wrow);
        fma_row8(acc + 12, pack2(a.w, a.w), wrow);
    }
#pragma unroll
    for (int j = 0; j < 4; j++) {
        int s = ssrc[eb + j];
        if (s >= 0) {
            const float4* br = (const float4*)(sb2 + c0);
            float* ar = g_agg + (size_t)s * ND + c0;
#pragma unroll
            for (int i = 0; i < 2; i++) {
                float4 bb = br[i];
                float x, y, z, w_;
                unpack2(acc[j * 4 + 2 * i], x, y);
                unpack2(acc[j * 4 + 2 * i + 1], z, w_);
                x += bb.x; y += bb.y; z += bb.z; w_ += bb.w;
                asm volatile(
                    "red.global.add.v4.f32 [%0], {%1, %2, %3, %4};"
                    :: "l"(ar + 4 * i), "f"(x), "f"(y), "f"(z), "f"(w_)
                    : "memory");
            }
        }
    }
}

// ---------------------------------------------------------------------------
// H2 = lrelu([nf, agg] @ upd_w1 + ub1). 64 rows/block, 512 thr (2 rows x 8 cols)
__global__ __launch_bounds__(512, 1) void upd1_kernel(
    const float* __restrict__ nf, const float* __restrict__ w1,
    const float* __restrict__ b1, int N)
{
    extern __shared__ float sm[];
    float* sw = sm;          // 256*128 = 32768
    float* sa = sm + 32768;  // 256 k * 68 = 17408
    int tid = threadIdx.x;
    int n0 = blockIdx.x * 64;

    for (int i = tid; i < 8192; i += 512)
        ((float4*)sw)[i] = ((const float4*)w1)[i];
    for (int i = tid; i < 2048; i += 512) {
        int r = i & 63, j = i >> 6, gn = n0 + r;
        float4 v = (gn < N) ? ((const float4*)nf)[(size_t)gn * 32 + j]
                            : make_float4(0.f, 0.f, 0.f, 0.f);
        float4 u = (gn < N) ? ((const float4*)g_agg)[(size_t)gn * 32 + j]
                            : make_float4(0.f, 0.f, 0.f, 0.f);
        sa[(4 * j + 0) * 68 + r] = v.x;
        sa[(4 * j + 1) * 68 + r] = v.y;
        sa[(4 * j + 2) * 68 + r] = v.z;
        sa[(4 * j + 3) * 68 + r] = v.w;
        sa[(128 + 4 * j + 0) * 68 + r] = u.x;
        sa[(128 + 4 * j + 1) * 68 + r] = u.y;
        sa[(128 + 4 * j + 2) * 68 + r] = u.z;
        sa[(128 + 4 * j + 3) * 68 + r] = u.w;
    }
    __syncthreads();

    int q = tid & 31, c0 = (tid >> 5) * 8, rb = 2 * q;
    ull acc[8];
#pragma unroll
    for (int i = 0; i < 8; i++) acc[i] = pack2(0.f, 0.f);
#pragma unroll 2
    for (int k = 0; k < 256; k++) {
        float2 a = *(float2*)(sa + k * 68 + rb);
        const float* wrow = sw + k * ND + c0;
        fma_row8(acc + 0, pack2(a.x, a.x), wrow);
        fma_row8(acc + 4, pack2(a.y, a.y), wrow);
    }
#pragma unroll
    for (int j = 0; j < 2; j++) {
        int gn = n0 + rb + j;
        if (gn < N) {
            const float4* br = (const float4*)(b1 + c0);
            float4* hr = (float4*)(g_H2 + (size_t)gn * ND + c0);
#pragma unroll
            for (int i = 0; i < 2; i++) {
                float4 bb = br[i];
                float x, y, z, w_;
                unpack2(acc[j * 4 + 2 * i], x, y);
                unpack2(acc[j * 4 + 2 * i + 1], z, w_);
                hr[i] = make_float4(lrelu(x + bb.x), lrelu(y + bb.y),
                                    lrelu(z + bb.z), lrelu(w_ + bb.w));
            }
        }
    }
}

// ---------------------------------------------------------------------------
// out = H2 @ upd_w2 + ub2. 128 rows/block, 512 thr (4 rows x 8 cols)
__global__ __launch_bounds__(512, 1) void upd2_kernel(
    const float* __restrict__ w2, const float* __restrict__ b2,
    float* __restrict__ out, int N)
{
    extern __shared__ float sm[];
    float* sw = sm;          // 128*128
    float* sa = sm + 16384;  // 128 k * 132
    int tid = threadIdx.x;
    int n0 = blockIdx.x * 128;

    for (int i = tid; i < 4096; i += 512)
        ((float4*)sw)[i] = ((const float4*)w2)[i];
    for (int i = tid; i < 4096; i += 512) {
        int r = i & 127, j = i >> 7, gn = n0 + r;
        float4 v = (gn < N) ? ((const float4*)g_H2)[(size_t)gn * 32 + j]
                            : make_float4(0.f, 0.f, 0.f, 0.f);
        sa[(4 * j + 0) * 132 + r] = v.x;
        sa[(4 * j + 1) * 132 + r] = v.y;
        sa[(4 * j + 2) * 132 + r] = v.z;
        sa[(4 * j + 3) * 132 + r] = v.w;
    }
    __syncthreads();

    int q = tid & 31, c0 = (tid >> 5) * 8, rb = 4 * q;
    ull acc[16];
#pragma unroll
    for (int i = 0; i < 16; i++) acc[i] = pack2(0.f, 0.f);
#pragma unroll 2
    for (int k = 0; k < 128; k++) {
        float4 a = *(float4*)(sa + k * 132 + rb);
        const float* wrow = sw + k * ND + c0;
        fma_row8(acc + 0,  pack2(a.x, a.x), wrow);
        fma_row8(acc + 4,  pack2(a.y, a.y), wrow);
        fma_row8(acc + 8,  pack2(a.z, a.z), wrow);
        fma_row8(acc + 12, pack2(a.w, a.w), wrow);
    }
#pragma unroll
    for (int j = 0; j < 4; j++) {
        int gn = n0 + rb + j;
        if (gn < N) {
            const float4* br = (const float4*)(b2 + c0);
            float4* orow = (float4*)(out + (size_t)gn * ND + c0);
#pragma unroll
            for (int i = 0; i < 2; i++) {
                float4 bb = br[i];
                float x, y, z, w_;
                unpack2(acc[j * 4 + 2 * i], x, y);
                unpack2(acc[j * 4 + 2 * i + 1], z, w_);
                orow[i] = make_float4(x + bb.x, y + bb.y, z + bb.z, w_ + bb.w);
            }
        }
    }
}

// ---------------------------------------------------------------------------
extern "C" void kernel_launch(void* const* d_in, const int* in_sizes, int n_in,
                              void* d_out, int out_size)
{
    const float* nf  = (const float*)d_in[0];
    const float* ef  = (const float*)d_in[1];
    const float* mw1 = (const float*)d_in[2];
    const float* mb1 = (const float*)d_in[3];
    const float* mw2 = (const float*)d_in[4];
    const float* mb2 = (const float*)d_in[5];
    const float* uw1 = (const float*)d_in[6];
    const float* ub1 = (const float*)d_in[7];
    const float* uw2 = (const float*)d_in[8];
    const float* ub2 = (const float*)d_in[9];
    const int* eidx  = (const int*)d_in[10];   // int32 (JAX x64 disabled)
    float* out = (float*)d_out;

    int N = in_sizes[0] / ND;
    int E = in_sizes[10] / 2;

    const int P_SM  = (16384 + 128 * 132) * 4;            // 133120
    const int E_SM  = (50176 + 256) * 4;                  // 201728
    const int U1_SM = (32768 + 256 * 68) * 4;             // 200704
    const int U2_SM = (16384 + 128 * 132) * 4;            // 133120

    cudaFuncSetAttribute(p_kernel,    cudaFuncAttributeMaxDynamicSharedMemorySize, P_SM);
    cudaFuncSetAttribute(edge_kernel, cudaFuncAttributeMaxDynamicSharedMemorySize, E_SM);
    cudaFuncSetAttribute(upd1_kernel, cudaFuncAttributeMaxDynamicSharedMemorySize, U1_SM);
    cudaFuncSetAttribute(upd2_kernel, cudaFuncAttributeMaxDynamicSharedMemorySize, U2_SM);

    int n4 = (N * ND) / 4;
    zero_kernel<<<(n4 + 255) / 256, 256>>>(n4);
    p_kernel<<<(N + 127) / 128, 512, P_SM>>>(nf, mw1, N);
    edge_kernel<<<(E + TE - 1) / TE, 512, E_SM>>>(ef, mw1, mb1, mw2, mb2, eidx, N, E);
    upd1_kernel<<<(N + 63) / 64, 512, U1_SM>>>(nf, uw1, ub1, N);
    upd2_kernel<<<(N + 127) / 128, 512, U2_SM>>>(uw2, ub2, out, N);
}